// round 3
// baseline (speedup 1.0000x reference)
#include <cuda_runtime.h>

#define N_NODES 50000
#define OUT_DIM 128
#define NNZ_X 800000
#define N_EDGES 1600000

// ---- persistent scratch (__device__ globals; no allocations) ----
__device__ float g_h[N_NODES * OUT_DIM];             // 25.6 MB intermediate
__device__ int   g_xcnt[N_NODES];
__device__ int   g_acnt[N_NODES];
__device__ int   g_xstart[N_NODES + 1];
__device__ int   g_astart[N_NODES + 1];
__device__ int   g_xcur[N_NODES];
__device__ int   g_acur[N_NODES];
__device__ int2  g_xs[NNZ_X];                         // {col, val bits} sorted by row
__device__ int2  g_as[N_EDGES];                       // {col, val bits} sorted by row

// ---- 0: zero the histograms (re-run every call: graph replay) ----
__global__ void init_kernel() {
    int idx = blockIdx.x * blockDim.x + threadIdx.x;
    int stride = gridDim.x * blockDim.x;
    for (int i = idx; i < N_NODES; i += stride) {
        g_xcnt[i] = 0;
        g_acnt[i] = 0;
    }
}

// ---- 1: histogram rows ----
__global__ void hist_kernel(const int* __restrict__ x_rows,
                            const int* __restrict__ adj_rows) {
    int idx = blockIdx.x * blockDim.x + threadIdx.x;
    int stride = gridDim.x * blockDim.x;
    for (int i = idx; i < NNZ_X; i += stride) atomicAdd(&g_xcnt[x_rows[i]], 1);
    for (int i = idx; i < N_EDGES; i += stride) atomicAdd(&g_acnt[adj_rows[i]], 1);
}

// ---- 2: exclusive scan (single block, 1024 threads) for both histograms ----
#define SCAN_T 1024
#define CHUNK 49   // 1024*49 >= 50000

__device__ __forceinline__ void scan_one(const int* __restrict__ cnt,
                                         int* __restrict__ start,
                                         int* __restrict__ cur,
                                         int* s) {
    int t = threadIdx.x;
    int lo = t * CHUNK;
    int hi = min(lo + CHUNK, N_NODES);
    int sum = 0;
    for (int i = lo; i < hi; i++) sum += cnt[i];
    s[t] = sum;
    __syncthreads();
    // Hillis-Steele inclusive scan
    for (int d = 1; d < SCAN_T; d <<= 1) {
        int v = (t >= d) ? s[t - d] : 0;
        __syncthreads();
        s[t] += v;
        __syncthreads();
    }
    int off = (t > 0) ? s[t - 1] : 0;
    for (int i = lo; i < hi; i++) {
        start[i] = off;
        cur[i] = off;
        off += cnt[i];
    }
    if (t == SCAN_T - 1) start[N_NODES] = s[SCAN_T - 1];
    __syncthreads();
}

__global__ void scan_kernel() {
    __shared__ int s[SCAN_T];
    scan_one(g_xcnt, g_xstart, g_xcur, s);
    scan_one(g_acnt, g_astart, g_acur, s);
}

// ---- 3: scatter into row-sorted order ----
__global__ void scatter_kernel(const int* __restrict__ x_rows,
                               const int* __restrict__ x_cols,
                               const float* __restrict__ x_vals,
                               const float* __restrict__ noise,
                               const int* __restrict__ adj_rows,
                               const int* __restrict__ adj_cols,
                               const float* __restrict__ adj_vals) {
    int idx = blockIdx.x * blockDim.x + threadIdx.x;
    int stride = gridDim.x * blockDim.x;
    for (int i = idx; i < NNZ_X; i += stride) {
        int r = x_rows[i];
        float v = x_vals[i] * floorf(1.0f + noise[i]);   // keep_prob=1 -> mask==1
        int pos = atomicAdd(&g_xcur[r], 1);
        g_xs[pos] = make_int2(x_cols[i], __float_as_int(v));
    }
    for (int i = idx; i < N_EDGES; i += stride) {
        int r = adj_rows[i];
        int pos = atomicAdd(&g_acur[r], 1);
        g_as[pos] = make_int2(adj_cols[i], __float_as_int(adj_vals[i]));
    }
}

// ---- 4: hop1  h[row] = sum v * W[col]   (warp per row, single store) ----
__global__ void hop1_kernel(const float4* __restrict__ W4) {
    int row = (blockIdx.x * blockDim.x + threadIdx.x) >> 5;
    int lane = threadIdx.x & 31;
    if (row >= N_NODES) return;
    int s0 = g_xstart[row], s1 = g_xstart[row + 1];
    float4 acc = make_float4(0.f, 0.f, 0.f, 0.f);
    int i = s0;
    for (; i + 4 <= s1; i += 4) {
        int2 e0 = g_xs[i], e1 = g_xs[i + 1], e2 = g_xs[i + 2], e3 = g_xs[i + 3];
        float4 w0 = W4[e0.x * 32 + lane];
        float4 w1 = W4[e1.x * 32 + lane];
        float4 w2 = W4[e2.x * 32 + lane];
        float4 w3 = W4[e3.x * 32 + lane];
        float v0 = __int_as_float(e0.y), v1 = __int_as_float(e1.y);
        float v2 = __int_as_float(e2.y), v3 = __int_as_float(e3.y);
        acc.x += v0 * w0.x + v1 * w1.x + v2 * w2.x + v3 * w3.x;
        acc.y += v0 * w0.y + v1 * w1.y + v2 * w2.y + v3 * w3.y;
        acc.z += v0 * w0.z + v1 * w1.z + v2 * w2.z + v3 * w3.z;
        acc.w += v0 * w0.w + v1 * w1.w + v2 * w2.w + v3 * w3.w;
    }
    for (; i < s1; i++) {
        int2 e = g_xs[i];
        float v = __int_as_float(e.y);
        float4 w = W4[e.x * 32 + lane];
        acc.x += v * w.x; acc.y += v * w.y; acc.z += v * w.z; acc.w += v * w.w;
    }
    reinterpret_cast<float4*>(g_h)[row * 32 + lane] = acc;
}

// ---- 5: hop2  out[row] = relu(sum w * h[col])   (warp per row, fused relu) ----
__global__ void hop2_kernel(float4* __restrict__ out4) {
    int row = (blockIdx.x * blockDim.x + threadIdx.x) >> 5;
    int lane = threadIdx.x & 31;
    if (row >= N_NODES) return;
    int s0 = g_astart[row], s1 = g_astart[row + 1];
    const float4* __restrict__ h4 = reinterpret_cast<const float4*>(g_h);
    float4 acc = make_float4(0.f, 0.f, 0.f, 0.f);
    int i = s0;
    for (; i + 4 <= s1; i += 4) {
        int2 e0 = g_as[i], e1 = g_as[i + 1], e2 = g_as[i + 2], e3 = g_as[i + 3];
        float4 a = h4[e0.x * 32 + lane];
        float4 b = h4[e1.x * 32 + lane];
        float4 c = h4[e2.x * 32 + lane];
        float4 d = h4[e3.x * 32 + lane];
        float v0 = __int_as_float(e0.y), v1 = __int_as_float(e1.y);
        float v2 = __int_as_float(e2.y), v3 = __int_as_float(e3.y);
        acc.x += v0 * a.x + v1 * b.x + v2 * c.x + v3 * d.x;
        acc.y += v0 * a.y + v1 * b.y + v2 * c.y + v3 * d.y;
        acc.z += v0 * a.z + v1 * b.z + v2 * c.z + v3 * d.z;
        acc.w += v0 * a.w + v1 * b.w + v2 * c.w + v3 * d.w;
    }
    for (; i < s1; i++) {
        int2 e = g_as[i];
        float v = __int_as_float(e.y);
        float4 a = h4[e.x * 32 + lane];
        acc.x += v * a.x; acc.y += v * a.y; acc.z += v * a.z; acc.w += v * a.w;
    }
    acc.x = fmaxf(acc.x, 0.f); acc.y = fmaxf(acc.y, 0.f);
    acc.z = fmaxf(acc.z, 0.f); acc.w = fmaxf(acc.w, 0.f);
    out4[row * 32 + lane] = acc;
}

extern "C" void kernel_launch(void* const* d_in, const int* in_sizes, int n_in,
                              void* d_out, int out_size) {
    const int*   x_rows   = (const int*)d_in[0];
    const int*   x_cols   = (const int*)d_in[1];
    const float* x_vals   = (const float*)d_in[2];
    const float* noise    = (const float*)d_in[3];
    const int*   adj_rows = (const int*)d_in[4];
    const int*   adj_cols = (const int*)d_in[5];
    const float* adj_vals = (const float*)d_in[6];
    const float* W        = (const float*)d_in[7];
    float4* out4 = (float4*)d_out;

    init_kernel<<<98, 512>>>();
    hist_kernel<<<2048, 256>>>(x_rows, adj_rows);
    scan_kernel<<<1, SCAN_T>>>();
    scatter_kernel<<<2048, 256>>>(x_rows, x_cols, x_vals, noise,
                                  adj_rows, adj_cols, adj_vals);

    // warp per row: 50000 warps -> 6250 blocks of 8 warps
    hop1_kernel<<<(N_NODES * 32 + 255) / 256, 256>>>(reinterpret_cast<const float4*>(W));
    hop2_kernel<<<(N_NODES * 32 + 255) / 256, 256>>>(out4);
}

// round 4
// speedup vs baseline: 1.4488x; 1.4488x over previous
#include <cuda_runtime.h>
#include <cuda_fp16.h>

#define N_NODES 50000
#define OUT_DIM 128
#define NNZ_X 800000
#define N_EDGES 1600000

// ---- persistent scratch (__device__ globals; no allocations) ----
__device__ __half g_hh[N_NODES * OUT_DIM];           // 12.8 MB intermediate (fp16)
__device__ int   g_xcnt[N_NODES];
__device__ int   g_acnt[N_NODES];
__device__ int   g_xstart[N_NODES + 1];
__device__ int   g_astart[N_NODES + 1];
__device__ int   g_xcur[N_NODES];
__device__ int   g_acur[N_NODES];
__device__ int2  g_xs[NNZ_X];                         // {col, val bits} sorted by row
__device__ int2  g_as[N_EDGES];                       // {col, val bits} sorted by row

// ---- 0: zero the histograms (re-run every graph replay) ----
__global__ void init_kernel() {
    int idx = blockIdx.x * blockDim.x + threadIdx.x;
    int stride = gridDim.x * blockDim.x;
    for (int i = idx; i < N_NODES; i += stride) {
        g_xcnt[i] = 0;
        g_acnt[i] = 0;
    }
}

// ---- 1: histogram rows (vectorized int4 reads; REDG atomics) ----
__global__ void hist_kernel(const int4* __restrict__ x_rows4,
                            const int4* __restrict__ adj_rows4) {
    int idx = blockIdx.x * blockDim.x + threadIdx.x;
    int stride = gridDim.x * blockDim.x;
    for (int i = idx; i < NNZ_X / 4; i += stride) {
        int4 r = x_rows4[i];
        atomicAdd(&g_xcnt[r.x], 1);
        atomicAdd(&g_xcnt[r.y], 1);
        atomicAdd(&g_xcnt[r.z], 1);
        atomicAdd(&g_xcnt[r.w], 1);
    }
    for (int i = idx; i < N_EDGES / 4; i += stride) {
        int4 r = adj_rows4[i];
        atomicAdd(&g_acnt[r.x], 1);
        atomicAdd(&g_acnt[r.y], 1);
        atomicAdd(&g_acnt[r.z], 1);
        atomicAdd(&g_acnt[r.w], 1);
    }
}

// ---- 2: exclusive scan; 2 blocks, one per histogram ----
#define SCAN_T 1024
#define CHUNK 49   // 1024*49 >= 50000

__device__ __forceinline__ void scan_one(const int* __restrict__ cnt,
                                         int* __restrict__ start,
                                         int* __restrict__ cur,
                                         int* s) {
    int t = threadIdx.x;
    int lo = t * CHUNK;
    int hi = min(lo + CHUNK, N_NODES);
    int sum = 0;
    for (int i = lo; i < hi; i++) sum += cnt[i];
    s[t] = sum;
    __syncthreads();
    for (int d = 1; d < SCAN_T; d <<= 1) {
        int v = (t >= d) ? s[t - d] : 0;
        __syncthreads();
        s[t] += v;
        __syncthreads();
    }
    int off = (t > 0) ? s[t - 1] : 0;
    for (int i = lo; i < hi; i++) {
        start[i] = off;
        cur[i] = off;
        off += cnt[i];
    }
    if (t == SCAN_T - 1) start[N_NODES] = s[SCAN_T - 1];
}

__global__ void scan_kernel() {
    __shared__ int s[SCAN_T];
    if (blockIdx.x == 0) scan_one(g_xcnt, g_xstart, g_xcur, s);
    else                 scan_one(g_acnt, g_astart, g_acur, s);
}

// ---- 3: scatter into row-sorted order (vectorized reads) ----
__global__ void scatter_kernel(const int4* __restrict__ x_rows4,
                               const int4* __restrict__ x_cols4,
                               const float4* __restrict__ x_vals4,
                               const float4* __restrict__ noise4,
                               const int4* __restrict__ adj_rows4,
                               const int4* __restrict__ adj_cols4,
                               const float4* __restrict__ adj_vals4) {
    int idx = blockIdx.x * blockDim.x + threadIdx.x;
    int stride = gridDim.x * blockDim.x;
    for (int i = idx; i < NNZ_X / 4; i += stride) {
        int4 r = x_rows4[i];
        int4 c = x_cols4[i];
        float4 v = x_vals4[i];
        float4 n = noise4[i];
        v.x *= floorf(1.0f + n.x);  // keep_prob=1 -> mask==1 (kept for faithfulness)
        v.y *= floorf(1.0f + n.y);
        v.z *= floorf(1.0f + n.z);
        v.w *= floorf(1.0f + n.w);
        g_xs[atomicAdd(&g_xcur[r.x], 1)] = make_int2(c.x, __float_as_int(v.x));
        g_xs[atomicAdd(&g_xcur[r.y], 1)] = make_int2(c.y, __float_as_int(v.y));
        g_xs[atomicAdd(&g_xcur[r.z], 1)] = make_int2(c.z, __float_as_int(v.z));
        g_xs[atomicAdd(&g_xcur[r.w], 1)] = make_int2(c.w, __float_as_int(v.w));
    }
    for (int i = idx; i < N_EDGES / 4; i += stride) {
        int4 r = adj_rows4[i];
        int4 c = adj_cols4[i];
        float4 v = adj_vals4[i];
        g_as[atomicAdd(&g_acur[r.x], 1)] = make_int2(c.x, __float_as_int(v.x));
        g_as[atomicAdd(&g_acur[r.y], 1)] = make_int2(c.y, __float_as_int(v.y));
        g_as[atomicAdd(&g_acur[r.z], 1)] = make_int2(c.z, __float_as_int(v.z));
        g_as[atomicAdd(&g_acur[r.w], 1)] = make_int2(c.w, __float_as_int(v.w));
    }
}

// ---- 4: hop1  h[row] = sum v * W[col]  -> fp16 store (warp per row) ----
__global__ void hop1_kernel(const float4* __restrict__ W4) {
    int row = (blockIdx.x * blockDim.x + threadIdx.x) >> 5;
    int lane = threadIdx.x & 31;
    if (row >= N_NODES) return;
    int s0 = g_xstart[row], s1 = g_xstart[row + 1];
    float4 acc = make_float4(0.f, 0.f, 0.f, 0.f);
    int i = s0;
    for (; i + 4 <= s1; i += 4) {
        int2 e0 = g_xs[i], e1 = g_xs[i + 1], e2 = g_xs[i + 2], e3 = g_xs[i + 3];
        float4 w0 = W4[e0.x * 32 + lane];
        float4 w1 = W4[e1.x * 32 + lane];
        float4 w2 = W4[e2.x * 32 + lane];
        float4 w3 = W4[e3.x * 32 + lane];
        float v0 = __int_as_float(e0.y), v1 = __int_as_float(e1.y);
        float v2 = __int_as_float(e2.y), v3 = __int_as_float(e3.y);
        acc.x += v0 * w0.x + v1 * w1.x + v2 * w2.x + v3 * w3.x;
        acc.y += v0 * w0.y + v1 * w1.y + v2 * w2.y + v3 * w3.y;
        acc.z += v0 * w0.z + v1 * w1.z + v2 * w2.z + v3 * w3.z;
        acc.w += v0 * w0.w + v1 * w1.w + v2 * w2.w + v3 * w3.w;
    }
    for (; i < s1; i++) {
        int2 e = g_xs[i];
        float v = __int_as_float(e.y);
        float4 w = W4[e.x * 32 + lane];
        acc.x += v * w.x; acc.y += v * w.y; acc.z += v * w.z; acc.w += v * w.w;
    }
    __half2 lo = __floats2half2_rn(acc.x, acc.y);
    __half2 hi = __floats2half2_rn(acc.z, acc.w);
    uint2 u;
    u.x = *reinterpret_cast<unsigned*>(&lo);
    u.y = *reinterpret_cast<unsigned*>(&hi);
    reinterpret_cast<uint2*>(g_hh)[row * 32 + lane] = u;   // 4 halfs per lane, 256B/row
}

// ---- 5: hop2  out[row] = relu(sum w * h_fp16[col])  (warp per row, x8 unroll) ----
__device__ __forceinline__ void fma_h(float4& acc, float v, uint2 u) {
    __half2 lo = *reinterpret_cast<__half2*>(&u.x);
    __half2 hi = *reinterpret_cast<__half2*>(&u.y);
    float2 f0 = __half22float2(lo);
    float2 f1 = __half22float2(hi);
    acc.x += v * f0.x; acc.y += v * f0.y;
    acc.z += v * f1.x; acc.w += v * f1.y;
}

__global__ void hop2_kernel(float4* __restrict__ out4) {
    int row = (blockIdx.x * blockDim.x + threadIdx.x) >> 5;
    int lane = threadIdx.x & 31;
    if (row >= N_NODES) return;
    int s0 = g_astart[row], s1 = g_astart[row + 1];
    const uint2* __restrict__ h2 = reinterpret_cast<const uint2*>(g_hh);
    float4 acc = make_float4(0.f, 0.f, 0.f, 0.f);
    int i = s0;
    for (; i + 8 <= s1; i += 8) {
        int2 e[8];
        uint2 u[8];
#pragma unroll
        for (int k = 0; k < 8; k++) e[k] = g_as[i + k];
#pragma unroll
        for (int k = 0; k < 8; k++) u[k] = h2[e[k].x * 32 + lane];
#pragma unroll
        for (int k = 0; k < 8; k++) fma_h(acc, __int_as_float(e[k].y), u[k]);
    }
    for (; i < s1; i++) {
        int2 e = g_as[i];
        fma_h(acc, __int_as_float(e.y), h2[e.x * 32 + lane]);
    }
    acc.x = fmaxf(acc.x, 0.f); acc.y = fmaxf(acc.y, 0.f);
    acc.z = fmaxf(acc.z, 0.f); acc.w = fmaxf(acc.w, 0.f);
    out4[row * 32 + lane] = acc;
}

extern "C" void kernel_launch(void* const* d_in, const int* in_sizes, int n_in,
                              void* d_out, int out_size) {
    const int*   x_rows   = (const int*)d_in[0];
    const int*   x_cols   = (const int*)d_in[1];
    const float* x_vals   = (const float*)d_in[2];
    const float* noise    = (const float*)d_in[3];
    const int*   adj_rows = (const int*)d_in[4];
    const int*   adj_cols = (const int*)d_in[5];
    const float* adj_vals = (const float*)d_in[6];
    const float* W        = (const float*)d_in[7];
    float4* out4 = (float4*)d_out;

    init_kernel<<<98, 512>>>();
    hist_kernel<<<1184, 256>>>((const int4*)x_rows, (const int4*)adj_rows);
    scan_kernel<<<2, SCAN_T>>>();
    scatter_kernel<<<1184, 256>>>((const int4*)x_rows, (const int4*)x_cols,
                                  (const float4*)x_vals, (const float4*)noise,
                                  (const int4*)adj_rows, (const int4*)adj_cols,
                                  (const float4*)adj_vals);

    hop1_kernel<<<(N_NODES * 32 + 255) / 256, 256>>>(reinterpret_cast<const float4*>(W));
    hop2_kernel<<<(N_NODES * 32 + 255) / 256, 256>>>(out4);
}